// round 15
// baseline (speedup 1.0000x reference)
#include <cuda_runtime.h>
#include <cuda_bf16.h>
#include <mma.h>
#include <math.h>
#include <stdint.h>

using namespace nvcuda;

#define NN_ 50000
#define EE_ 600000
#define CC_ 128
#define LL_ 3
#define HID_ 32
#define NCLS_ 7
#define NBY_ 391                   // ceil(50000/128)
#define PERSIST_CTAS 296           // 2 per SM x 148 SMs

// ======================= device scratch =======================
__device__ float d_g[NN_ * 512];          // [rz_sum(256) | xn(128) | hn(128)], bias NOT applied
__device__ unsigned short d_hsp_hi[NN_ * CC_];
__device__ unsigned short d_hsp_lo[NN_ * CC_];
__device__ unsigned short d_agg_hi[NN_ * CC_];
__device__ unsigned short d_agg_lo[NN_ * CC_];
__device__ unsigned short d_Brz_hi[LL_ * 256 * 256];
__device__ unsigned short d_Brz_lo[LL_ * 256 * 256];
__device__ unsigned short d_Bxn_hi[LL_ * 128 * 128];
__device__ unsigned short d_Bxn_lo[LL_ * 128 * 128];
__device__ unsigned short d_Bhn_hi[128 * 128];
__device__ unsigned short d_Bhn_lo[128 * 128];
__device__ float d_bias[512];
// CSR
__device__ int   d_counts[NN_];
__device__ int   d_rowptr[NN_ + 1];
__device__ int   d_cursor[NN_];
__device__ int   d_csr_eid[EE_];
__device__ int   d_csr_src[EE_];
__device__ float d_csr_w[EE_];

__device__ __forceinline__ float bfu(unsigned short u) {
    return __bfloat162float(__ushort_as_bfloat16(u));
}
__device__ __forceinline__ void split2(float v, unsigned short& hi, unsigned short& lo) {
    __nv_bfloat16 h = __float2bfloat16(v);
    float r = v - __bfloat162float(h);
    hi = __bfloat16_as_ushort(h);
    lo = __bfloat16_as_ushort(__float2bfloat16(r));
}
__device__ __forceinline__ uint32_t smem_u32(const void* p) {
    uint32_t a;
    asm("{ .reg .u64 t; cvta.to.shared.u64 t, %1; cvt.u32.u64 %0, t; }" : "=r"(a) : "l"(p));
    return a;
}
__device__ __forceinline__ void cpa16(uint32_t d, const void* s, int sz) {
    asm volatile("cp.async.cg.shared.global [%0], [%1], 16, %2;\n" :: "r"(d), "l"(s), "r"(sz));
}
#define CP_COMMIT() asm volatile("cp.async.commit_group;\n" ::: "memory")
#define CP_WAIT1()  asm volatile("cp.async.wait_group 1;\n" ::: "memory")
#define CP_WAIT0()  asm volatile("cp.async.wait_group 0;\n" ::: "memory")

// ======================= init =======================
#define R1_ (LL_ * 384 * 128)
#define R2_ (LL_ * 256 * 128)
#define R3_ (128 * 128)
#define R4_ 512
#define R5_ NN_
#define R6_ (NN_ * CC_ / 4)

__global__ void init_kernel(const float* __restrict__ cw, const float* __restrict__ wih,
                            const float* __restrict__ whh, const float* __restrict__ bih,
                            const float* __restrict__ bhh, const float* __restrict__ x) {
    int idx = blockIdx.x * blockDim.x + threadIdx.x;
    if (idx < R1_) {
        int l = idx / 49152;
        int rem = idx % 49152;
        int j = rem / 128, kin = rem % 128;
        const float4* Wl = reinterpret_cast<const float4*>(cw + l * CC_ * CC_ + kin * CC_);
        const float4* wj = reinterpret_cast<const float4*>(wih + j * CC_);
        float s = 0.f;
#pragma unroll
        for (int t = 0; t < 32; t++) {
            float4 a = Wl[t], b = wj[t];
            s += a.x * b.x + a.y * b.y + a.z * b.z + a.w * b.w;
        }
        if (j < 256) {
            int dst = l * 65536 + j * 256 + kin;
            split2(s, d_Brz_hi[dst], d_Brz_lo[dst]);
        } else {
            int dst = l * 16384 + (j - 256) * 128 + kin;
            split2(s, d_Bxn_hi[dst], d_Bxn_lo[dst]);
        }
        return;
    }
    idx -= R1_;
    if (idx < R2_) {
        int l = idx / 32768;
        int rem = idx % 32768;
        int j = rem / 128, k = rem % 128;
        int dst = l * 65536 + j * 256 + 128 + k;
        split2(whh[j * 128 + k], d_Brz_hi[dst], d_Brz_lo[dst]);
        return;
    }
    idx -= R2_;
    if (idx < R3_) {
        int j = idx / 128, k = idx % 128;
        split2(whh[(256 + j) * 128 + k], d_Bhn_hi[idx], d_Bhn_lo[idx]);
        return;
    }
    idx -= R3_;
    if (idx < R4_) {
        float b;
        if (idx < 256)      b = bih[idx] + bhh[idx];
        else if (idx < 384) b = bih[idx];
        else                b = bhh[idx - 128];
        d_bias[idx] = b;
        return;
    }
    idx -= R4_;
    if (idx < R5_) { d_counts[idx] = 0; return; }
    idx -= R5_;
    if (idx < R6_) {
        float4 v = reinterpret_cast<const float4*>(x)[idx];
        ushort4 h, l;
        split2(v.x, h.x, l.x); split2(v.y, h.y, l.y);
        split2(v.z, h.z, l.z); split2(v.w, h.w, l.w);
        reinterpret_cast<ushort4*>(d_hsp_hi)[idx] = h;
        reinterpret_cast<ushort4*>(d_hsp_lo)[idx] = l;
    }
}

// ======================= CSR build =======================
__global__ void hist_kernel(const int* __restrict__ ei) {
    int e = blockIdx.x * blockDim.x + threadIdx.x;
    if (e < EE_) atomicAdd(&d_counts[ei[EE_ + e]], 1);
}

__global__ void scan_kernel() {
    __shared__ int part[1024];
    const int CH = (NN_ + 1023) / 1024;
    int t = threadIdx.x;
    int start = t * CH;
    int end = start + CH; if (end > NN_) end = NN_;
    int s = 0;
    for (int i = start; i < end; i++) s += d_counts[i];
    part[t] = s;
    __syncthreads();
    if (t == 0) {
        int acc = 0;
        for (int i = 0; i < 1024; i++) { int v = part[i]; part[i] = acc; acc += v; }
        d_rowptr[NN_] = acc;
    }
    __syncthreads();
    int acc = part[t];
    for (int i = start; i < end; i++) {
        d_rowptr[i] = acc; d_cursor[i] = acc; acc += d_counts[i];
    }
}

__global__ void scatter_kernel(const int* __restrict__ ei) {
    int e = blockIdx.x * blockDim.x + threadIdx.x;
    if (e < EE_) {
        int dst = ei[EE_ + e];
        int pos = atomicAdd(&d_cursor[dst], 1);
        d_csr_eid[pos] = e;
    }
}

// sort segment eids (deterministic order) AND materialize src/w directly
__global__ void sortfill_kernel(const int* __restrict__ ei, const float* __restrict__ ew) {
    int n = blockIdx.x * blockDim.x + threadIdx.x;
    if (n >= NN_) return;
    int lo = d_rowptr[n], hi = d_rowptr[n + 1];
    int cnt = hi - lo;
    if (cnt <= 0) return;
    if (cnt <= 64) {
        int buf[64];
        for (int i = 0; i < cnt; i++) buf[i] = d_csr_eid[lo + i];
        for (int i = 1; i < cnt; i++) {
            int k = buf[i];
            int j = i - 1;
            while (j >= 0 && buf[j] > k) { buf[j + 1] = buf[j]; j--; }
            buf[j + 1] = k;
        }
        for (int i = 0; i < cnt; i++) {
            int eid = buf[i];
            d_csr_src[lo + i] = ei[eid];
            d_csr_w[lo + i]   = ew[eid];
        }
    } else {
        for (int i = lo + 1; i < hi; i++) {
            int ke = d_csr_eid[i];
            int j = i - 1;
            while (j >= lo && d_csr_eid[j] > ke) {
                d_csr_eid[j + 1] = d_csr_eid[j];
                j--;
            }
            d_csr_eid[j + 1] = ke;
        }
        for (int i = lo; i < hi; i++) {
            int eid = d_csr_eid[i];
            d_csr_src[i] = ei[eid];
            d_csr_w[i]   = ew[eid];
        }
    }
}

// ======================= aggregation: broadcast loads + 2-edge unroll =======================
__device__ __forceinline__ float4 agg_row(const float* __restrict__ xext, int use_x,
                                          int s, int lane) {
    float4 v;
    if (use_x) {
        v = __ldg(reinterpret_cast<const float4*>(xext + (size_t)s * CC_ + lane * 4));
    } else {
        size_t o = (size_t)s * CC_ + lane * 4;
        ushort4 vh = *reinterpret_cast<const ushort4*>(d_hsp_hi + o);
        ushort4 vl = *reinterpret_cast<const ushort4*>(d_hsp_lo + o);
        v.x = bfu(vh.x) + bfu(vl.x); v.y = bfu(vh.y) + bfu(vl.y);
        v.z = bfu(vh.z) + bfu(vl.z); v.w = bfu(vh.w) + bfu(vl.w);
    }
    return v;
}

__global__ void aggregate_kernel(const float* __restrict__ xext, int use_x) {
    int gw = (blockIdx.x * blockDim.x + threadIdx.x) >> 5;
    int lane = threadIdx.x & 31;
    if (gw >= NN_) return;
    int lo = d_rowptr[gw], hi = d_rowptr[gw + 1];
    float4 a0 = make_float4(0.f, 0.f, 0.f, 0.f);
    float4 a1 = make_float4(0.f, 0.f, 0.f, 0.f);
    int e = lo;
    for (; e + 2 <= hi; e += 2) {
        int s0 = __ldg(&d_csr_src[e]);
        int s1 = __ldg(&d_csr_src[e + 1]);
        float w0 = __ldg(&d_csr_w[e]);
        float w1 = __ldg(&d_csr_w[e + 1]);
        float4 v0 = agg_row(xext, use_x, s0, lane);
        float4 v1 = agg_row(xext, use_x, s1, lane);
        a0.x += w0 * v0.x; a0.y += w0 * v0.y; a0.z += w0 * v0.z; a0.w += w0 * v0.w;
        a1.x += w1 * v1.x; a1.y += w1 * v1.y; a1.z += w1 * v1.z; a1.w += w1 * v1.w;
    }
    if (e < hi) {
        int s0 = __ldg(&d_csr_src[e]);
        float w0 = __ldg(&d_csr_w[e]);
        float4 v0 = agg_row(xext, use_x, s0, lane);
        a0.x += w0 * v0.x; a0.y += w0 * v0.y; a0.z += w0 * v0.z; a0.w += w0 * v0.w;
    }
    a0.x += a1.x; a0.y += a1.y; a0.z += a1.z; a0.w += a1.w;
    ushort4 h, l;
    split2(a0.x, h.x, l.x); split2(a0.y, h.y, l.y);
    split2(a0.z, h.z, l.z); split2(a0.w, h.w, l.w);
    size_t o = ((size_t)gw * CC_ + lane * 4) / 4;
    reinterpret_cast<ushort4*>(d_agg_hi)[o] = h;
    reinterpret_cast<ushort4*>(d_agg_lo)[o] = l;
}

// ======================= GRU GEMM: persistent CTAs, 64x64 warp tiles =======================
#define TSK 40
#define TILE_E (128 * TSK)
#define BUF_E  (4 * TILE_E)
#define GEMM_SMEM (2 * BUF_E * 2)   // 81920 bytes
#define EPI_S 132

template <int NCK>
__device__ __forceinline__ void gemm_body(
    char* smem, uint32_t su, int row0, int outc0,
    const unsigned short* A0hi, const unsigned short* A0lo,
    const unsigned short* A1hi, const unsigned short* A1lo,
    const unsigned short* Bhi, const unsigned short* Blo) {
    const int Kb = NCK * 32;
    __nv_bfloat16* s = reinterpret_cast<__nv_bfloat16*>(smem);
    float* sC = reinterpret_cast<float*>(smem);
    int tid = threadIdx.x, wid = tid >> 5;     // 128 threads, 4 warps
    int warp_m = wid >> 1, warp_n = wid & 1;   // 2x2 warp grid, 64x64 tiles

    wmma::fragment<wmma::accumulator, 16, 16, 16, float> acc[4][4];
#pragma unroll
    for (int i = 0; i < 4; i++)
#pragma unroll
        for (int j = 0; j < 4; j++) wmma::fill_fragment(acc[i][j], 0.f);

    auto prefetch = [&](int c, int bsel) {
        int k0 = c * 32;
        const unsigned short* Ah = A0hi;
        const unsigned short* Al = A0lo;
        int koff = k0;
        if (k0 >= 128) { Ah = A1hi; Al = A1lo; koff = k0 - 128; }
        uint32_t sb = su + (uint32_t)bsel * (BUF_E * 2);
#pragma unroll
        for (int t = 0; t < 4; t++) {
            int v = tid + t * 128;
            int r = v >> 2, c8 = (v & 3) << 3;
            uint32_t so = (uint32_t)(r * TSK + c8) * 2;
            int grow = row0 + r;
            int ok = (grow < NN_) ? 16 : 0;
            size_t ga = (size_t)grow * CC_ + koff + c8;
            cpa16(sb + so,         Ah + ga, ok);
            cpa16(sb + 10240 + so, Al + ga, ok);
            size_t gb = (size_t)r * Kb + k0 + c8;
            cpa16(sb + 20480 + so, Bhi + gb, 16);
            cpa16(sb + 30720 + so, Blo + gb, 16);
        }
    };

    prefetch(0, 0);
    CP_COMMIT();

#pragma unroll
    for (int c = 0; c < NCK; c++) {
        if (c + 1 < NCK) {
            prefetch(c + 1, (c + 1) & 1);
            CP_COMMIT();
            CP_WAIT1();
        } else {
            CP_WAIT0();
        }
        __syncthreads();

        const __nv_bfloat16* sb   = s + (c & 1) * BUF_E;
        const __nv_bfloat16* tAhi = sb;
        const __nv_bfloat16* tAlo = sb + TILE_E;
        const __nv_bfloat16* tBhi = sb + 2 * TILE_E;
        const __nv_bfloat16* tBlo = sb + 3 * TILE_E;

#pragma unroll
        for (int ks = 0; ks < 2; ks++) {
            wmma::fragment<wmma::matrix_a, 16, 16, 16, __nv_bfloat16, wmma::row_major> fahi[4], falo[4];
#pragma unroll
            for (int i = 0; i < 4; i++) {
                int off = (warp_m * 64 + i * 16) * TSK + ks * 16;
                wmma::load_matrix_sync(fahi[i], tAhi + off, TSK);
                wmma::load_matrix_sync(falo[i], tAlo + off, TSK);
            }
#pragma unroll
            for (int j = 0; j < 4; j++) {
                wmma::fragment<wmma::matrix_b, 16, 16, 16, __nv_bfloat16, wmma::col_major> fbhi, fblo;
                int off = (warp_n * 64 + j * 16) * TSK + ks * 16;
                wmma::load_matrix_sync(fbhi, tBhi + off, TSK);
                wmma::load_matrix_sync(fblo, tBlo + off, TSK);
#pragma unroll
                for (int i = 0; i < 4; i++) {
                    wmma::mma_sync(acc[i][j], fahi[i], fbhi, acc[i][j]);
                    wmma::mma_sync(acc[i][j], fahi[i], fblo, acc[i][j]);
                    wmma::mma_sync(acc[i][j], falo[i], fbhi, acc[i][j]);
                }
            }
        }
        __syncthreads();
    }

    // ---- epilogue (no bias; gate adds it) ----
    if (row0 + 128 <= NN_) {
#pragma unroll
        for (int i = 0; i < 4; i++)
#pragma unroll
            for (int j = 0; j < 4; j++) {
                float* p = d_g + (size_t)(row0 + warp_m * 64 + i * 16) * 512
                           + outc0 + warp_n * 64 + j * 16;
                wmma::store_matrix_sync(p, acc[i][j], 512, wmma::mem_row_major);
            }
    } else {
#pragma unroll
        for (int i = 0; i < 4; i++)
#pragma unroll
            for (int j = 0; j < 4; j++) {
                float* p = sC + (warp_m * 64 + i * 16) * EPI_S + warp_n * 64 + j * 16;
                wmma::store_matrix_sync(p, acc[i][j], EPI_S, wmma::mem_row_major);
            }
        __syncthreads();
#pragma unroll
        for (int t = 0; t < 32; t++) {
            int v = tid + t * 128;
            int r = v >> 5;
            int c4 = (v & 31) << 2;
            int grow = row0 + r;
            if (grow >= NN_) continue;
            float4 o;
            o.x = sC[r * EPI_S + c4 + 0];
            o.y = sC[r * EPI_S + c4 + 1];
            o.z = sC[r * EPI_S + c4 + 2];
            o.w = sC[r * EPI_S + c4 + 3];
            *reinterpret_cast<float4*>(d_g + (size_t)grow * 512 + outc0 + c4) = o;
        }
        __syncthreads();   // protect sC from next item's prefetch into buf 0
    }
}

__global__ void __launch_bounds__(128, 2)
gru_gemm_kernel(int layer) {
    extern __shared__ __align__(16) char smem[];
    uint32_t su = smem_u32(smem);

    // persistent loop over work items: item = iy*4 + bx
    for (int item = blockIdx.x; item < 4 * NBY_; item += gridDim.x) {
        int bx = item & 3;
        int row0 = (item >> 2) * 128;
        if (bx < 2) {
            gemm_body<8>(smem, su, row0, bx * 128,
                         d_agg_hi, d_agg_lo, d_hsp_hi, d_hsp_lo,
                         d_Brz_hi + layer * 65536 + bx * 128 * 256,
                         d_Brz_lo + layer * 65536 + bx * 128 * 256);
        } else if (bx == 2) {
            gemm_body<4>(smem, su, row0, 256,
                         d_agg_hi, d_agg_lo, nullptr, nullptr,
                         d_Bxn_hi + layer * 16384, d_Bxn_lo + layer * 16384);
        } else {
            gemm_body<4>(smem, su, row0, 384,
                         d_hsp_hi, d_hsp_lo, nullptr, nullptr,
                         d_Bhn_hi, d_Bhn_lo);
        }
    }
}

// ======================= GRU gate: 4 channels/thread, vectorized =======================
__global__ void gate_kernel(const float* __restrict__ xext, int use_x) {
    int idx = blockIdx.x * blockDim.x + threadIdx.x;   // NN_*32 threads
    if (idx >= NN_ * 32) return;
    int node = idx >> 5;
    int c4   = (idx & 31) << 2;
    const float* g = d_g + (size_t)node * 512;
    float4 rv = __ldg(reinterpret_cast<const float4*>(g + c4));
    float4 zv = __ldg(reinterpret_cast<const float4*>(g + 128 + c4));
    float4 xn = __ldg(reinterpret_cast<const float4*>(g + 256 + c4));
    float4 hn = __ldg(reinterpret_cast<const float4*>(g + 384 + c4));
    float4 br = __ldg(reinterpret_cast<const float4*>(d_bias + c4));
    float4 bz = __ldg(reinterpret_cast<const float4*>(d_bias + 128 + c4));
    float4 bx = __ldg(reinterpret_cast<const float4*>(d_bias + 256 + c4));
    float4 bh = __ldg(reinterpret_cast<const float4*>(d_bias + 384 + c4));
    size_t ho = (size_t)node * CC_ + c4;
    float hp[4];
    if (use_x) {
        float4 v = __ldg(reinterpret_cast<const float4*>(xext + ho));
        hp[0] = v.x; hp[1] = v.y; hp[2] = v.z; hp[3] = v.w;
    } else {
        ushort4 vh = *reinterpret_cast<const ushort4*>(d_hsp_hi + ho);
        ushort4 vl = *reinterpret_cast<const ushort4*>(d_hsp_lo + ho);
        hp[0] = bfu(vh.x) + bfu(vl.x); hp[1] = bfu(vh.y) + bfu(vl.y);
        hp[2] = bfu(vh.z) + bfu(vl.z); hp[3] = bfu(vh.w) + bfu(vl.w);
    }
    float rr[4] = {rv.x + br.x, rv.y + br.y, rv.z + br.z, rv.w + br.w};
    float zz[4] = {zv.x + bz.x, zv.y + bz.y, zv.z + bz.z, zv.w + bz.w};
    float xx[4] = {xn.x + bx.x, xn.y + bx.y, xn.z + bx.z, xn.w + bx.w};
    float hh[4] = {hn.x + bh.x, hn.y + bh.y, hn.z + bh.z, hn.w + bh.w};
    ushort4 oh, ol;
    unsigned short* po = reinterpret_cast<unsigned short*>(&oh);
    unsigned short* pl = reinterpret_cast<unsigned short*>(&ol);
#pragma unroll
    for (int q = 0; q < 4; q++) {
        float r = 1.f / (1.f + __expf(-rr[q]));
        float z = 1.f / (1.f + __expf(-zz[q]));
        float n = tanhf(xx[q] + r * hh[q]);
        split2((1.f - z) * n + z * hp[q], po[q], pl[q]);
    }
    *reinterpret_cast<ushort4*>(d_hsp_hi + ho) = oh;
    *reinterpret_cast<ushort4*>(d_hsp_lo + ho) = ol;
}

// ======================= fused MLP + head =======================
__global__ void __launch_bounds__(256)
mlp_head_kernel(const float* __restrict__ w0, const float* __restrict__ b0,
                const float* __restrict__ w1, const float* __restrict__ b1,
                const float* __restrict__ w2, const float* __restrict__ b2,
                const float* __restrict__ w3, const float* __restrict__ b3,
                float* __restrict__ out) {
    __shared__ float sw0[HID_ * CC_];
    __shared__ float sw1[HID_ * HID_];
    __shared__ float sw2[HID_ * HID_];
    __shared__ float sw3[NCLS_ * HID_];
    __shared__ float sb0[HID_], sb1[HID_], sb2[HID_], sb3[NCLS_];
    int tid = threadIdx.x;
    for (int i = tid; i < HID_ * CC_; i += 256) sw0[i] = w0[i];
    for (int i = tid; i < HID_ * HID_; i += 256) { sw1[i] = w1[i]; sw2[i] = w2[i]; }
    for (int i = tid; i < NCLS_ * HID_; i += 256) sw3[i] = w3[i];
    if (tid < HID_) { sb0[tid] = b0[tid]; sb1[tid] = b1[tid]; sb2[tid] = b2[tid]; }
    if (tid < NCLS_) sb3[tid] = b3[tid];
    __syncthreads();

    int n = blockIdx.x * 256 + tid;
    if (n >= NN_) return;

    float y0[HID_];
#pragma unroll
    for (int o = 0; o < HID_; o++) y0[o] = sb0[o];

#pragma unroll
    for (int ck = 0; ck < 8; ck++) {
        float hb[16];
        size_t go = (size_t)n * CC_ + ck * 16;
        ushort4 h0 = *reinterpret_cast<const ushort4*>(d_hsp_hi + go);
        ushort4 h1 = *reinterpret_cast<const ushort4*>(d_hsp_hi + go + 4);
        ushort4 h2 = *reinterpret_cast<const ushort4*>(d_hsp_hi + go + 8);
        ushort4 h3 = *reinterpret_cast<const ushort4*>(d_hsp_hi + go + 12);
        ushort4 l0 = *reinterpret_cast<const ushort4*>(d_hsp_lo + go);
        ushort4 l1 = *reinterpret_cast<const ushort4*>(d_hsp_lo + go + 4);
        ushort4 l2 = *reinterpret_cast<const ushort4*>(d_hsp_lo + go + 8);
        ushort4 l3 = *reinterpret_cast<const ushort4*>(d_hsp_lo + go + 12);
        hb[0]  = bfu(h0.x) + bfu(l0.x); hb[1]  = bfu(h0.y) + bfu(l0.y);
        hb[2]  = bfu(h0.z) + bfu(l0.z); hb[3]  = bfu(h0.w) + bfu(l0.w);
        hb[4]  = bfu(h1.x) + bfu(l1.x); hb[5]  = bfu(h1.y) + bfu(l1.y);
        hb[6]  = bfu(h1.z) + bfu(l1.z); hb[7]  = bfu(h1.w) + bfu(l1.w);
        hb[8]  = bfu(h2.x) + bfu(l2.x); hb[9]  = bfu(h2.y) + bfu(l2.y);
        hb[10] = bfu(h2.z) + bfu(l2.z); hb[11] = bfu(h2.w) + bfu(l2.w);
        hb[12] = bfu(h3.x) + bfu(l3.x); hb[13] = bfu(h3.y) + bfu(l3.y);
        hb[14] = bfu(h3.z) + bfu(l3.z); hb[15] = bfu(h3.w) + bfu(l3.w);
#pragma unroll
        for (int o = 0; o < HID_; o++) {
            const float4* wr = reinterpret_cast<const float4*>(sw0 + o * CC_ + ck * 16);
            float4 w4;
            w4 = wr[0]; y0[o] += hb[0] * w4.x + hb[1] * w4.y + hb[2] * w4.z + hb[3] * w4.w;
            w4 = wr[1]; y0[o] += hb[4] * w4.x + hb[5] * w4.y + hb[6] * w4.z + hb[7] * w4.w;
            w4 = wr[2]; y0[o] += hb[8] * w4.x + hb[9] * w4.y + hb[10] * w4.z + hb[11] * w4.w;
            w4 = wr[3]; y0[o] += hb[12] * w4.x + hb[13] * w4.y + hb[14] * w4.z + hb[15] * w4.w;
        }
    }
#pragma unroll
    for (int o = 0; o < HID_; o++) y0[o] = tanhf(y0[o]);

    float y1[HID_];
#pragma unroll
    for (int o = 0; o < HID_; o++) {
        float s = sb1[o];
        const float4* wr = reinterpret_cast<const float4*>(sw1 + o * HID_);
#pragma unroll
        for (int k4 = 0; k4 < HID_ / 4; k4++) {
            float4 w4 = wr[k4];
            s += y0[k4 * 4] * w4.x + y0[k4 * 4 + 1] * w4.y + y0[k4 * 4 + 2] * w4.z + y0[k4 * 4 + 3] * w4.w;
        }
        y1[o] = tanhf(s);
    }
#pragma unroll
    for (int o = 0; o < HID_; o++) {
        float s = sb2[o];
        const float4* wr = reinterpret_cast<const float4*>(sw2 + o * HID_);
#pragma unroll
        for (int k4 = 0; k4 < HID_ / 4; k4++) {
            float4 w4 = wr[k4];
            s += y1[k4 * 4] * w4.x + y1[k4 * 4 + 1] * w4.y + y1[k4 * 4 + 2] * w4.z + y1[k4 * 4 + 3] * w4.w;
        }
        y0[o] = tanhf(s);
    }

    float logit[NCLS_];
    float mx = -1e30f;
#pragma unroll
    for (int c = 0; c < NCLS_; c++) {
        float s = sb3[c];
        const float4* wr = reinterpret_cast<const float4*>(sw3 + c * HID_);
#pragma unroll
        for (int k4 = 0; k4 < HID_ / 4; k4++) {
            float4 w4 = wr[k4];
            s += y0[k4 * 4] * w4.x + y0[k4 * 4 + 1] * w4.y + y0[k4 * 4 + 2] * w4.z + y0[k4 * 4 + 3] * w4.w;
        }
        logit[c] = s;
        mx = fmaxf(mx, s);
    }
    float se = 0.f;
#pragma unroll
    for (int c = 0; c < NCLS_; c++) se += expf(logit[c] - mx);
    float lse = logf(se) + mx;
#pragma unroll
    for (int c = 0; c < NCLS_; c++) out[(size_t)n * NCLS_ + c] = logit[c] - lse;
}

// ======================= host: kernel launches only =======================
extern "C" void kernel_launch(void* const* d_in, const int* in_sizes, int n_in,
                              void* d_out, int out_size) {
    const float* x    = (const float*)d_in[0];
    const int*   ei   = (const int*)  d_in[1];
    const float* ew   = (const float*)d_in[2];
    const float* cw   = (const float*)d_in[3];
    const float* w_ih = (const float*)d_in[4];
    const float* w_hh = (const float*)d_in[5];
    const float* b_ih = (const float*)d_in[6];
    const float* b_hh = (const float*)d_in[7];
    const float* w0   = (const float*)d_in[8];
    const float* b0   = (const float*)d_in[9];
    const float* w1   = (const float*)d_in[10];
    const float* b1   = (const float*)d_in[11];
    const float* w2   = (const float*)d_in[12];
    const float* b2   = (const float*)d_in[13];
    const float* w3   = (const float*)d_in[14];
    const float* b3   = (const float*)d_in[15];
    float* out = (float*)d_out;

    cudaFuncSetAttribute(gru_gemm_kernel, cudaFuncAttributeMaxDynamicSharedMemorySize,
                         GEMM_SMEM);

    // init (weights/bias/counts/x-split)
    {
        int total = R1_ + R2_ + R3_ + R4_ + R5_ + R6_;
        init_kernel<<<(total + 255) / 256, 256>>>(cw, w_ih, w_hh, b_ih, b_hh, x);
    }
    // CSR build
    hist_kernel<<<(EE_ + 255) / 256, 256>>>(ei);
    scan_kernel<<<1, 1024>>>();
    scatter_kernel<<<(EE_ + 255) / 256, 256>>>(ei);
    sortfill_kernel<<<(NN_ + 255) / 256, 256>>>(ei, ew);

    for (int l = 0; l < LL_; l++) {
        aggregate_kernel<<<(NN_ * 32 + 255) / 256, 256>>>(x, l == 0 ? 1 : 0);
        gru_gemm_kernel<<<PERSIST_CTAS, 128, GEMM_SMEM>>>(l);
        gate_kernel<<<(NN_ * 32 + 255) / 256, 256>>>(x, l == 0 ? 1 : 0);
    }

    mlp_head_kernel<<<(NN_ + 255) / 256, 256>>>(w0, b0, w1, b1, w2, b2, w3, b3, out);
}

// round 16
// speedup vs baseline: 1.1095x; 1.1095x over previous
#include <cuda_runtime.h>
#include <cuda_bf16.h>
#include <mma.h>
#include <math.h>
#include <stdint.h>

using namespace nvcuda;

#define NN_ 50000
#define EE_ 600000
#define CC_ 128
#define LL_ 3
#define HID_ 32
#define NCLS_ 7

// ======================= device scratch =======================
__device__ float d_g[NN_ * 512];          // [rz_sum(256) | xn(128) | hn(128)], bias NOT applied
__device__ unsigned short d_hsp_hi[NN_ * CC_];
__device__ unsigned short d_hsp_lo[NN_ * CC_];
__device__ unsigned short d_agg_hi[NN_ * CC_];
__device__ unsigned short d_agg_lo[NN_ * CC_];
__device__ unsigned short d_Brz_hi[LL_ * 256 * 256];
__device__ unsigned short d_Brz_lo[LL_ * 256 * 256];
__device__ unsigned short d_Bxn_hi[LL_ * 128 * 128];
__device__ unsigned short d_Bxn_lo[LL_ * 128 * 128];
__device__ unsigned short d_Bhn_hi[128 * 128];
__device__ unsigned short d_Bhn_lo[128 * 128];
__device__ float d_bias[512];
// CSR
__device__ int   d_counts[NN_];
__device__ int   d_rowptr[NN_ + 1];
__device__ int   d_cursor[NN_];
__device__ int   d_csr_eid[EE_];
__device__ int   d_csr_src[EE_];
__device__ float d_csr_w[EE_];

__device__ __forceinline__ float bfu(unsigned short u) {
    return __bfloat162float(__ushort_as_bfloat16(u));
}
__device__ __forceinline__ void split2(float v, unsigned short& hi, unsigned short& lo) {
    __nv_bfloat16 h = __float2bfloat16(v);
    float r = v - __bfloat162float(h);
    hi = __bfloat16_as_ushort(h);
    lo = __bfloat16_as_ushort(__float2bfloat16(r));
}
__device__ __forceinline__ uint32_t smem_u32(const void* p) {
    uint32_t a;
    asm("{ .reg .u64 t; cvta.to.shared.u64 t, %1; cvt.u32.u64 %0, t; }" : "=r"(a) : "l"(p));
    return a;
}
__device__ __forceinline__ void cpa16(uint32_t d, const void* s, int sz) {
    asm volatile("cp.async.cg.shared.global [%0], [%1], 16, %2;\n" :: "r"(d), "l"(s), "r"(sz));
}
#define CP_COMMIT() asm volatile("cp.async.commit_group;\n" ::: "memory")
#define CP_WAIT0()  asm volatile("cp.async.wait_group 0;\n" ::: "memory")

// ======================= init =======================
#define R1_ (LL_ * 384 * 128)
#define R2_ (LL_ * 256 * 128)
#define R3_ (128 * 128)
#define R4_ 512
#define R5_ NN_
#define R6_ (NN_ * CC_ / 4)

__global__ void init_kernel(const float* __restrict__ cw, const float* __restrict__ wih,
                            const float* __restrict__ whh, const float* __restrict__ bih,
                            const float* __restrict__ bhh, const float* __restrict__ x) {
    int idx = blockIdx.x * blockDim.x + threadIdx.x;
    if (idx < R1_) {
        int l = idx / 49152;
        int rem = idx % 49152;
        int j = rem / 128, kin = rem % 128;
        const float4* Wl = reinterpret_cast<const float4*>(cw + l * CC_ * CC_ + kin * CC_);
        const float4* wj = reinterpret_cast<const float4*>(wih + j * CC_);
        float s = 0.f;
#pragma unroll
        for (int t = 0; t < 32; t++) {
            float4 a = Wl[t], b = wj[t];
            s += a.x * b.x + a.y * b.y + a.z * b.z + a.w * b.w;
        }
        if (j < 256) {
            int dst = l * 65536 + j * 256 + kin;
            split2(s, d_Brz_hi[dst], d_Brz_lo[dst]);
        } else {
            int dst = l * 16384 + (j - 256) * 128 + kin;
            split2(s, d_Bxn_hi[dst], d_Bxn_lo[dst]);
        }
        return;
    }
    idx -= R1_;
    if (idx < R2_) {
        int l = idx / 32768;
        int rem = idx % 32768;
        int j = rem / 128, k = rem % 128;
        int dst = l * 65536 + j * 256 + 128 + k;
        split2(whh[j * 128 + k], d_Brz_hi[dst], d_Brz_lo[dst]);
        return;
    }
    idx -= R2_;
    if (idx < R3_) {
        int j = idx / 128, k = idx % 128;
        split2(whh[(256 + j) * 128 + k], d_Bhn_hi[idx], d_Bhn_lo[idx]);
        return;
    }
    idx -= R3_;
    if (idx < R4_) {
        float b;
        if (idx < 256)      b = bih[idx] + bhh[idx];
        else if (idx < 384) b = bih[idx];
        else                b = bhh[idx - 128];
        d_bias[idx] = b;
        return;
    }
    idx -= R4_;
    if (idx < R5_) { d_counts[idx] = 0; return; }
    idx -= R5_;
    if (idx < R6_) {
        float4 v = reinterpret_cast<const float4*>(x)[idx];
        ushort4 h, l;
        split2(v.x, h.x, l.x); split2(v.y, h.y, l.y);
        split2(v.z, h.z, l.z); split2(v.w, h.w, l.w);
        reinterpret_cast<ushort4*>(d_hsp_hi)[idx] = h;
        reinterpret_cast<ushort4*>(d_hsp_lo)[idx] = l;
    }
}

// ======================= CSR build =======================
__global__ void hist_kernel(const int* __restrict__ ei) {
    int e = blockIdx.x * blockDim.x + threadIdx.x;
    if (e < EE_) atomicAdd(&d_counts[ei[EE_ + e]], 1);
}

__global__ void scan_kernel() {
    __shared__ int part[1024];
    const int CH = (NN_ + 1023) / 1024;
    int t = threadIdx.x;
    int start = t * CH;
    int end = start + CH; if (end > NN_) end = NN_;
    int s = 0;
    for (int i = start; i < end; i++) s += d_counts[i];
    part[t] = s;
    __syncthreads();
    if (t == 0) {
        int acc = 0;
        for (int i = 0; i < 1024; i++) { int v = part[i]; part[i] = acc; acc += v; }
        d_rowptr[NN_] = acc;
    }
    __syncthreads();
    int acc = part[t];
    for (int i = start; i < end; i++) {
        d_rowptr[i] = acc; d_cursor[i] = acc; acc += d_counts[i];
    }
}

__global__ void scatter_kernel(const int* __restrict__ ei) {
    int e = blockIdx.x * blockDim.x + threadIdx.x;
    if (e < EE_) {
        int dst = ei[EE_ + e];
        int pos = atomicAdd(&d_cursor[dst], 1);
        d_csr_eid[pos] = e;
    }
}

// sort segment eids (deterministic order) AND materialize src/w directly
__global__ void sortfill_kernel(const int* __restrict__ ei, const float* __restrict__ ew) {
    int n = blockIdx.x * blockDim.x + threadIdx.x;
    if (n >= NN_) return;
    int lo = d_rowptr[n], hi = d_rowptr[n + 1];
    int cnt = hi - lo;
    if (cnt <= 0) return;
    if (cnt <= 64) {
        int buf[64];
        for (int i = 0; i < cnt; i++) buf[i] = d_csr_eid[lo + i];
        for (int i = 1; i < cnt; i++) {
            int k = buf[i];
            int j = i - 1;
            while (j >= 0 && buf[j] > k) { buf[j + 1] = buf[j]; j--; }
            buf[j + 1] = k;
        }
        for (int i = 0; i < cnt; i++) {
            int eid = buf[i];
            d_csr_src[lo + i] = ei[eid];
            d_csr_w[lo + i]   = ew[eid];
        }
    } else {
        for (int i = lo + 1; i < hi; i++) {
            int ke = d_csr_eid[i];
            int j = i - 1;
            while (j >= lo && d_csr_eid[j] > ke) {
                d_csr_eid[j + 1] = d_csr_eid[j];
                j--;
            }
            d_csr_eid[j + 1] = ke;
        }
        for (int i = lo; i < hi; i++) {
            int eid = d_csr_eid[i];
            d_csr_src[i] = ei[eid];
            d_csr_w[i]   = ew[eid];
        }
    }
}

// ======================= aggregation: broadcast loads + 2-edge unroll =======================
__device__ __forceinline__ float4 agg_row(const float* __restrict__ xext, int use_x,
                                          int s, int lane) {
    float4 v;
    if (use_x) {
        v = __ldg(reinterpret_cast<const float4*>(xext + (size_t)s * CC_ + lane * 4));
    } else {
        size_t o = (size_t)s * CC_ + lane * 4;
        ushort4 vh = *reinterpret_cast<const ushort4*>(d_hsp_hi + o);
        ushort4 vl = *reinterpret_cast<const ushort4*>(d_hsp_lo + o);
        v.x = bfu(vh.x) + bfu(vl.x); v.y = bfu(vh.y) + bfu(vl.y);
        v.z = bfu(vh.z) + bfu(vl.z); v.w = bfu(vh.w) + bfu(vl.w);
    }
    return v;
}

__global__ void aggregate_kernel(const float* __restrict__ xext, int use_x) {
    int gw = (blockIdx.x * blockDim.x + threadIdx.x) >> 5;
    int lane = threadIdx.x & 31;
    if (gw >= NN_) return;
    int lo = d_rowptr[gw], hi = d_rowptr[gw + 1];
    float4 a0 = make_float4(0.f, 0.f, 0.f, 0.f);
    float4 a1 = make_float4(0.f, 0.f, 0.f, 0.f);
    int e = lo;
    for (; e + 2 <= hi; e += 2) {
        int s0 = __ldg(&d_csr_src[e]);
        int s1 = __ldg(&d_csr_src[e + 1]);
        float w0 = __ldg(&d_csr_w[e]);
        float w1 = __ldg(&d_csr_w[e + 1]);
        float4 v0 = agg_row(xext, use_x, s0, lane);
        float4 v1 = agg_row(xext, use_x, s1, lane);
        a0.x += w0 * v0.x; a0.y += w0 * v0.y; a0.z += w0 * v0.z; a0.w += w0 * v0.w;
        a1.x += w1 * v1.x; a1.y += w1 * v1.y; a1.z += w1 * v1.z; a1.w += w1 * v1.w;
    }
    if (e < hi) {
        int s0 = __ldg(&d_csr_src[e]);
        float w0 = __ldg(&d_csr_w[e]);
        float4 v0 = agg_row(xext, use_x, s0, lane);
        a0.x += w0 * v0.x; a0.y += w0 * v0.y; a0.z += w0 * v0.z; a0.w += w0 * v0.w;
    }
    a0.x += a1.x; a0.y += a1.y; a0.z += a1.z; a0.w += a1.w;
    ushort4 h, l;
    split2(a0.x, h.x, l.x); split2(a0.y, h.y, l.y);
    split2(a0.z, h.z, l.z); split2(a0.w, h.w, l.w);
    size_t o = ((size_t)gw * CC_ + lane * 4) / 4;
    reinterpret_cast<ushort4*>(d_agg_hi)[o] = h;
    reinterpret_cast<ushort4*>(d_agg_lo)[o] = l;
}

// ======================= GRU GEMM: grid (4, Ny), 64x64 warp tiles, single-sync pipe =======================
#define TSK 40
#define TILE_E (128 * TSK)
#define BUF_E  (4 * TILE_E)
#define GEMM_SMEM (2 * BUF_E * 2)   // 81920 bytes
#define EPI_S 132

template <int NCK>
__device__ __forceinline__ void gemm_body(
    char* smem, uint32_t su, int row0, int outc0,
    const unsigned short* A0hi, const unsigned short* A0lo,
    const unsigned short* A1hi, const unsigned short* A1lo,
    const unsigned short* Bhi, const unsigned short* Blo) {
    const int Kb = NCK * 32;
    __nv_bfloat16* s = reinterpret_cast<__nv_bfloat16*>(smem);
    float* sC = reinterpret_cast<float*>(smem);
    int tid = threadIdx.x, wid = tid >> 5;     // 128 threads, 4 warps
    int warp_m = wid >> 1, warp_n = wid & 1;   // 2x2 warp grid, 64x64 tiles

    wmma::fragment<wmma::accumulator, 16, 16, 16, float> acc[4][4];
#pragma unroll
    for (int i = 0; i < 4; i++)
#pragma unroll
        for (int j = 0; j < 4; j++) wmma::fill_fragment(acc[i][j], 0.f);

    auto prefetch = [&](int c, int bsel) {
        int k0 = c * 32;
        const unsigned short* Ah = A0hi;
        const unsigned short* Al = A0lo;
        int koff = k0;
        if (k0 >= 128) { Ah = A1hi; Al = A1lo; koff = k0 - 128; }
        uint32_t sb = su + (uint32_t)bsel * (BUF_E * 2);
#pragma unroll
        for (int t = 0; t < 4; t++) {
            int v = tid + t * 128;
            int r = v >> 2, c8 = (v & 3) << 3;
            uint32_t so = (uint32_t)(r * TSK + c8) * 2;
            int grow = row0 + r;
            int ok = (grow < NN_) ? 16 : 0;
            size_t ga = (size_t)grow * CC_ + koff + c8;
            cpa16(sb + so,         Ah + ga, ok);
            cpa16(sb + 10240 + so, Al + ga, ok);
            size_t gb = (size_t)r * Kb + k0 + c8;
            cpa16(sb + 20480 + so, Bhi + gb, 16);
            cpa16(sb + 30720 + so, Blo + gb, 16);
        }
    };

    prefetch(0, 0);
    CP_COMMIT();

#pragma unroll
    for (int c = 0; c < NCK; c++) {
        // wait for buffer c, make visible to all warps
        CP_WAIT0();
        __syncthreads();
        // issue next prefetch (into other buffer); safe: all warps finished compute c-1
        if (c + 1 < NCK) {
            prefetch(c + 1, (c + 1) & 1);
            CP_COMMIT();
        }

        const __nv_bfloat16* sb   = s + (c & 1) * BUF_E;
        const __nv_bfloat16* tAhi = sb;
        const __nv_bfloat16* tAlo = sb + TILE_E;
        const __nv_bfloat16* tBhi = sb + 2 * TILE_E;
        const __nv_bfloat16* tBlo = sb + 3 * TILE_E;

#pragma unroll
        for (int ks = 0; ks < 2; ks++) {
            wmma::fragment<wmma::matrix_a, 16, 16, 16, __nv_bfloat16, wmma::row_major> fahi[4], falo[4];
#pragma unroll
            for (int i = 0; i < 4; i++) {
                int off = (warp_m * 64 + i * 16) * TSK + ks * 16;
                wmma::load_matrix_sync(fahi[i], tAhi + off, TSK);
                wmma::load_matrix_sync(falo[i], tAlo + off, TSK);
            }
#pragma unroll
            for (int j = 0; j < 4; j++) {
                wmma::fragment<wmma::matrix_b, 16, 16, 16, __nv_bfloat16, wmma::col_major> fbhi, fblo;
                int off = (warp_n * 64 + j * 16) * TSK + ks * 16;
                wmma::load_matrix_sync(fbhi, tBhi + off, TSK);
                wmma::load_matrix_sync(fblo, tBlo + off, TSK);
#pragma unroll
                for (int i = 0; i < 4; i++) {
                    wmma::mma_sync(acc[i][j], fahi[i], fbhi, acc[i][j]);
                    wmma::mma_sync(acc[i][j], fahi[i], fblo, acc[i][j]);
                    wmma::mma_sync(acc[i][j], falo[i], fbhi, acc[i][j]);
                }
            }
        }
    }

    // ---- epilogue (no bias; gate adds it) ----
    if (row0 + 128 <= NN_) {
        // direct fragment store to global; no smem hazard, no sync needed
#pragma unroll
        for (int i = 0; i < 4; i++)
#pragma unroll
            for (int j = 0; j < 4; j++) {
                float* p = d_g + (size_t)(row0 + warp_m * 64 + i * 16) * 512
                           + outc0 + warp_n * 64 + j * 16;
                wmma::store_matrix_sync(p, acc[i][j], 512, wmma::mem_row_major);
            }
    } else {
        __syncthreads();   // other warps may still read A/B smem aliased by sC
#pragma unroll
        for (int i = 0; i < 4; i++)
#pragma unroll
            for (int j = 0; j < 4; j++) {
                float* p = sC + (warp_m * 64 + i * 16) * EPI_S + warp_n * 64 + j * 16;
                wmma::store_matrix_sync(p, acc[i][j], EPI_S, wmma::mem_row_major);
            }
        __syncthreads();
#pragma unroll
        for (int t = 0; t < 32; t++) {
            int v = tid + t * 128;
            int r = v >> 5;
            int c4 = (v & 31) << 2;
            int grow = row0 + r;
            if (grow >= NN_) continue;
            float4 o;
            o.x = sC[r * EPI_S + c4 + 0];
            o.y = sC[r * EPI_S + c4 + 1];
            o.z = sC[r * EPI_S + c4 + 2];
            o.w = sC[r * EPI_S + c4 + 3];
            *reinterpret_cast<float4*>(d_g + (size_t)grow * 512 + outc0 + c4) = o;
        }
    }
}

__global__ void __launch_bounds__(128, 2)
gru_gemm_kernel(int layer) {
    extern __shared__ __align__(16) char smem[];
    uint32_t su = smem_u32(smem);
    int bx = blockIdx.x;
    int row0 = blockIdx.y * 128;

    if (bx < 2) {
        gemm_body<8>(smem, su, row0, bx * 128,
                     d_agg_hi, d_agg_lo, d_hsp_hi, d_hsp_lo,
                     d_Brz_hi + layer * 65536 + bx * 128 * 256,
                     d_Brz_lo + layer * 65536 + bx * 128 * 256);
    } else if (bx == 2) {
        gemm_body<4>(smem, su, row0, 256,
                     d_agg_hi, d_agg_lo, nullptr, nullptr,
                     d_Bxn_hi + layer * 16384, d_Bxn_lo + layer * 16384);
    } else {
        gemm_body<4>(smem, su, row0, 384,
                     d_hsp_hi, d_hsp_lo, nullptr, nullptr,
                     d_Bhn_hi, d_Bhn_lo);
    }
}

// ======================= GRU gate: 4 channels/thread, vectorized =======================
__global__ void gate_kernel(const float* __restrict__ xext, int use_x) {
    int idx = blockIdx.x * blockDim.x + threadIdx.x;   // NN_*32 threads
    if (idx >= NN_ * 32) return;
    int node = idx >> 5;
    int c4   = (idx & 31) << 2;
    const float* g = d_g + (size_t)node * 512;
    float4 rv = __ldg(reinterpret_cast<const float4*>(g + c4));
    float4 zv = __ldg(reinterpret_cast<const float4*>(g + 128 + c4));
    float4 xn = __ldg(reinterpret_cast<const float4*>(g + 256 + c4));
    float4 hn = __ldg(reinterpret_cast<const float4*>(g + 384 + c4));
    float4 br = __ldg(reinterpret_cast<const float4*>(d_bias + c4));
    float4 bz = __ldg(reinterpret_cast<const float4*>(d_bias + 128 + c4));
    float4 bx = __ldg(reinterpret_cast<const float4*>(d_bias + 256 + c4));
    float4 bh = __ldg(reinterpret_cast<const float4*>(d_bias + 384 + c4));
    size_t ho = (size_t)node * CC_ + c4;
    float hp[4];
    if (use_x) {
        float4 v = __ldg(reinterpret_cast<const float4*>(xext + ho));
        hp[0] = v.x; hp[1] = v.y; hp[2] = v.z; hp[3] = v.w;
    } else {
        ushort4 vh = *reinterpret_cast<const ushort4*>(d_hsp_hi + ho);
        ushort4 vl = *reinterpret_cast<const ushort4*>(d_hsp_lo + ho);
        hp[0] = bfu(vh.x) + bfu(vl.x); hp[1] = bfu(vh.y) + bfu(vl.y);
        hp[2] = bfu(vh.z) + bfu(vl.z); hp[3] = bfu(vh.w) + bfu(vl.w);
    }
    float rr[4] = {rv.x + br.x, rv.y + br.y, rv.z + br.z, rv.w + br.w};
    float zz[4] = {zv.x + bz.x, zv.y + bz.y, zv.z + bz.z, zv.w + bz.w};
    float xx[4] = {xn.x + bx.x, xn.y + bx.y, xn.z + bx.z, xn.w + bx.w};
    float hh[4] = {hn.x + bh.x, hn.y + bh.y, hn.z + bh.z, hn.w + bh.w};
    ushort4 oh, ol;
    unsigned short* po = reinterpret_cast<unsigned short*>(&oh);
    unsigned short* pl = reinterpret_cast<unsigned short*>(&ol);
#pragma unroll
    for (int q = 0; q < 4; q++) {
        float r = 1.f / (1.f + __expf(-rr[q]));
        float z = 1.f / (1.f + __expf(-zz[q]));
        float n = tanhf(xx[q] + r * hh[q]);
        split2((1.f - z) * n + z * hp[q], po[q], pl[q]);
    }
    *reinterpret_cast<ushort4*>(d_hsp_hi + ho) = oh;
    *reinterpret_cast<ushort4*>(d_hsp_lo + ho) = ol;
}

// ======================= fused MLP + head =======================
__global__ void __launch_bounds__(256)
mlp_head_kernel(const float* __restrict__ w0, const float* __restrict__ b0,
                const float* __restrict__ w1, const float* __restrict__ b1,
                const float* __restrict__ w2, const float* __restrict__ b2,
                const float* __restrict__ w3, const float* __restrict__ b3,
                float* __restrict__ out) {
    __shared__ float sw0[HID_ * CC_];
    __shared__ float sw1[HID_ * HID_];
    __shared__ float sw2[HID_ * HID_];
    __shared__ float sw3[NCLS_ * HID_];
    __shared__ float sb0[HID_], sb1[HID_], sb2[HID_], sb3[NCLS_];
    int tid = threadIdx.x;
    for (int i = tid; i < HID_ * CC_; i += 256) sw0[i] = w0[i];
    for (int i = tid; i < HID_ * HID_; i += 256) { sw1[i] = w1[i]; sw2[i] = w2[i]; }
    for (int i = tid; i < NCLS_ * HID_; i += 256) sw3[i] = w3[i];
    if (tid < HID_) { sb0[tid] = b0[tid]; sb1[tid] = b1[tid]; sb2[tid] = b2[tid]; }
    if (tid < NCLS_) sb3[tid] = b3[tid];
    __syncthreads();

    int n = blockIdx.x * 256 + tid;
    if (n >= NN_) return;

    float y0[HID_];
#pragma unroll
    for (int o = 0; o < HID_; o++) y0[o] = sb0[o];

#pragma unroll
    for (int ck = 0; ck < 8; ck++) {
        float hb[16];
        size_t go = (size_t)n * CC_ + ck * 16;
        ushort4 h0 = *reinterpret_cast<const ushort4*>(d_hsp_hi + go);
        ushort4 h1 = *reinterpret_cast<const ushort4*>(d_hsp_hi + go + 4);
        ushort4 h2 = *reinterpret_cast<const ushort4*>(d_hsp_hi + go + 8);
        ushort4 h3 = *reinterpret_cast<const ushort4*>(d_hsp_hi + go + 12);
        ushort4 l0 = *reinterpret_cast<const ushort4*>(d_hsp_lo + go);
        ushort4 l1 = *reinterpret_cast<const ushort4*>(d_hsp_lo + go + 4);
        ushort4 l2 = *reinterpret_cast<const ushort4*>(d_hsp_lo + go + 8);
        ushort4 l3 = *reinterpret_cast<const ushort4*>(d_hsp_lo + go + 12);
        hb[0]  = bfu(h0.x) + bfu(l0.x); hb[1]  = bfu(h0.y) + bfu(l0.y);
        hb[2]  = bfu(h0.z) + bfu(l0.z); hb[3]  = bfu(h0.w) + bfu(l0.w);
        hb[4]  = bfu(h1.x) + bfu(l1.x); hb[5]  = bfu(h1.y) + bfu(l1.y);
        hb[6]  = bfu(h1.z) + bfu(l1.z); hb[7]  = bfu(h1.w) + bfu(l1.w);
        hb[8]  = bfu(h2.x) + bfu(l2.x); hb[9]  = bfu(h2.y) + bfu(l2.y);
        hb[10] = bfu(h2.z) + bfu(l2.z); hb[11] = bfu(h2.w) + bfu(l2.w);
        hb[12] = bfu(h3.x) + bfu(l3.x); hb[13] = bfu(h3.y) + bfu(l3.y);
        hb[14] = bfu(h3.z) + bfu(l3.z); hb[15] = bfu(h3.w) + bfu(l3.w);
#pragma unroll
        for (int o = 0; o < HID_; o++) {
            const float4* wr = reinterpret_cast<const float4*>(sw0 + o * CC_ + ck * 16);
            float4 w4;
            w4 = wr[0]; y0[o] += hb[0] * w4.x + hb[1] * w4.y + hb[2] * w4.z + hb[3] * w4.w;
            w4 = wr[1]; y0[o] += hb[4] * w4.x + hb[5] * w4.y + hb[6] * w4.z + hb[7] * w4.w;
            w4 = wr[2]; y0[o] += hb[8] * w4.x + hb[9] * w4.y + hb[10] * w4.z + hb[11] * w4.w;
            w4 = wr[3]; y0[o] += hb[12] * w4.x + hb[13] * w4.y + hb[14] * w4.z + hb[15] * w4.w;
        }
    }
#pragma unroll
    for (int o = 0; o < HID_; o++) y0[o] = tanhf(y0[o]);

    float y1[HID_];
#pragma unroll
    for (int o = 0; o < HID_; o++) {
        float s = sb1[o];
        const float4* wr = reinterpret_cast<const float4*>(sw1 + o * HID_);
#pragma unroll
        for (int k4 = 0; k4 < HID_ / 4; k4++) {
            float4 w4 = wr[k4];
            s += y0[k4 * 4] * w4.x + y0[k4 * 4 + 1] * w4.y + y0[k4 * 4 + 2] * w4.z + y0[k4 * 4 + 3] * w4.w;
        }
        y1[o] = tanhf(s);
    }
#pragma unroll
    for (int o = 0; o < HID_; o++) {
        float s = sb2[o];
        const float4* wr = reinterpret_cast<const float4*>(sw2 + o * HID_);
#pragma unroll
        for (int k4 = 0; k4 < HID_ / 4; k4++) {
            float4 w4 = wr[k4];
            s += y1[k4 * 4] * w4.x + y1[k4 * 4 + 1] * w4.y + y1[k4 * 4 + 2] * w4.z + y1[k4 * 4 + 3] * w4.w;
        }
        y0[o] = tanhf(s);
    }

    float logit[NCLS_];
    float mx = -1e30f;
#pragma unroll
    for (int c = 0; c < NCLS_; c++) {
        float s = sb3[c];
        const float4* wr = reinterpret_cast<const float4*>(sw3 + c * HID_);
#pragma unroll
        for (int k4 = 0; k4 < HID_ / 4; k4++) {
            float4 w4 = wr[k4];
            s += y0[k4 * 4] * w4.x + y0[k4 * 4 + 1] * w4.y + y0[k4 * 4 + 2] * w4.z + y0[k4 * 4 + 3] * w4.w;
        }
        logit[c] = s;
        mx = fmaxf(mx, s);
    }
    float se = 0.f;
#pragma unroll
    for (int c = 0; c < NCLS_; c++) se += expf(logit[c] - mx);
    float lse = logf(se) + mx;
#pragma unroll
    for (int c = 0; c < NCLS_; c++) out[(size_t)n * NCLS_ + c] = logit[c] - lse;
}

// ======================= host: kernel launches only =======================
extern "C" void kernel_launch(void* const* d_in, const int* in_sizes, int n_in,
                              void* d_out, int out_size) {
    const float* x    = (const float*)d_in[0];
    const int*   ei   = (const int*)  d_in[1];
    const float* ew   = (const float*)d_in[2];
    const float* cw   = (const float*)d_in[3];
    const float* w_ih = (const float*)d_in[4];
    const float* w_hh = (const float*)d_in[5];
    const float* b_ih = (const float*)d_in[6];
    const float* b_hh = (const float*)d_in[7];
    const float* w0   = (const float*)d_in[8];
    const float* b0   = (const float*)d_in[9];
    const float* w1   = (const float*)d_in[10];
    const float* b1   = (const float*)d_in[11];
    const float* w2   = (const float*)d_in[12];
    const float* b2   = (const float*)d_in[13];
    const float* w3   = (const float*)d_in[14];
    const float* b3   = (const float*)d_in[15];
    float* out = (float*)d_out;

    cudaFuncSetAttribute(gru_gemm_kernel, cudaFuncAttributeMaxDynamicSharedMemorySize,
                         GEMM_SMEM);

    // init (weights/bias/counts/x-split)
    {
        int total = R1_ + R2_ + R3_ + R4_ + R5_ + R6_;
        init_kernel<<<(total + 255) / 256, 256>>>(cw, w_ih, w_hh, b_ih, b_hh, x);
    }
    // CSR build
    hist_kernel<<<(EE_ + 255) / 256, 256>>>(ei);
    scan_kernel<<<1, 1024>>>();
    scatter_kernel<<<(EE_ + 255) / 256, 256>>>(ei);
    sortfill_kernel<<<(NN_ + 255) / 256, 256>>>(ei, ew);

    dim3 grid_g(4, (NN_ + 127) / 128);
    for (int l = 0; l < LL_; l++) {
        aggregate_kernel<<<(NN_ * 32 + 255) / 256, 256>>>(x, l == 0 ? 1 : 0);
        gru_gemm_kernel<<<grid_g, 128, GEMM_SMEM>>>(l);
        gate_kernel<<<(NN_ * 32 + 255) / 256, 256>>>(x, l == 0 ? 1 : 0);
    }

    mlp_head_kernel<<<(NN_ + 255) / 256, 256>>>(w0, b0, w1, b1, w2, b2, w3, b3, out);
}

// round 17
// speedup vs baseline: 1.1458x; 1.0327x over previous
#include <cuda_runtime.h>
#include <cuda_bf16.h>
#include <mma.h>
#include <math.h>
#include <stdint.h>

using namespace nvcuda;

#define NN_ 50000
#define EE_ 600000
#define CC_ 128
#define LL_ 3
#define HID_ 32
#define NCLS_ 7

// ======================= device scratch =======================
__device__ float d_g[NN_ * 512];          // [rz_sum(256) | xn(128) | hn(128)], bias NOT applied
__device__ unsigned short d_hsp_hi[NN_ * CC_];
__device__ unsigned short d_hsp_lo[NN_ * CC_];
__device__ unsigned short d_agg_hi[NN_ * CC_];
__device__ unsigned short d_agg_lo[NN_ * CC_];
__device__ unsigned short d_Brz_hi[LL_ * 256 * 256];
__device__ unsigned short d_Brz_lo[LL_ * 256 * 256];
__device__ unsigned short d_Bxn_hi[LL_ * 128 * 128];
__device__ unsigned short d_Bxn_lo[LL_ * 128 * 128];
__device__ unsigned short d_Bhn_hi[128 * 128];
__device__ unsigned short d_Bhn_lo[128 * 128];
__device__ float d_bias[512];
// CSR
__device__ int   d_counts[NN_];
__device__ int   d_rowptr[NN_ + 1];
__device__ int   d_cursor[NN_];
__device__ int   d_csr_eid[EE_];
__device__ int   d_csr_src[EE_];
__device__ float d_csr_w[EE_];

__device__ __forceinline__ float bfu(unsigned short u) {
    return __bfloat162float(__ushort_as_bfloat16(u));
}
__device__ __forceinline__ void split2(float v, unsigned short& hi, unsigned short& lo) {
    __nv_bfloat16 h = __float2bfloat16(v);
    float r = v - __bfloat162float(h);
    hi = __bfloat16_as_ushort(h);
    lo = __bfloat16_as_ushort(__float2bfloat16(r));
}
__device__ __forceinline__ uint32_t smem_u32(const void* p) {
    uint32_t a;
    asm("{ .reg .u64 t; cvta.to.shared.u64 t, %1; cvt.u32.u64 %0, t; }" : "=r"(a) : "l"(p));
    return a;
}
__device__ __forceinline__ void cpa16(uint32_t d, const void* s, int sz) {
    asm volatile("cp.async.cg.shared.global [%0], [%1], 16, %2;\n" :: "r"(d), "l"(s), "r"(sz));
}
#define CP_COMMIT() asm volatile("cp.async.commit_group;\n" ::: "memory")
#define CP_WAIT0()  asm volatile("cp.async.wait_group 0;\n" ::: "memory")

__device__ __forceinline__ float fast_tanh(float x) {
    float y;
    asm("tanh.approx.f32 %0, %1;" : "=f"(y) : "f"(x));
    return y;
}
__device__ __forceinline__ float fast_sigmoid(float x) {
    return 0.5f * fast_tanh(0.5f * x) + 0.5f;
}

// ======================= init =======================
#define R1_ (LL_ * 384 * 128)
#define R2_ (LL_ * 256 * 128)
#define R3_ (128 * 128)
#define R4_ 512
#define R5_ NN_
#define R6_ (NN_ * CC_ / 4)

__global__ void init_kernel(const float* __restrict__ cw, const float* __restrict__ wih,
                            const float* __restrict__ whh, const float* __restrict__ bih,
                            const float* __restrict__ bhh, const float* __restrict__ x) {
    int idx = blockIdx.x * blockDim.x + threadIdx.x;
    if (idx < R1_) {
        int l = idx / 49152;
        int rem = idx % 49152;
        int j = rem / 128, kin = rem % 128;
        const float4* Wl = reinterpret_cast<const float4*>(cw + l * CC_ * CC_ + kin * CC_);
        const float4* wj = reinterpret_cast<const float4*>(wih + j * CC_);
        float s = 0.f;
#pragma unroll
        for (int t = 0; t < 32; t++) {
            float4 a = Wl[t], b = wj[t];
            s += a.x * b.x + a.y * b.y + a.z * b.z + a.w * b.w;
        }
        if (j < 256) {
            int dst = l * 65536 + j * 256 + kin;
            split2(s, d_Brz_hi[dst], d_Brz_lo[dst]);
        } else {
            int dst = l * 16384 + (j - 256) * 128 + kin;
            split2(s, d_Bxn_hi[dst], d_Bxn_lo[dst]);
        }
        return;
    }
    idx -= R1_;
    if (idx < R2_) {
        int l = idx / 32768;
        int rem = idx % 32768;
        int j = rem / 128, k = rem % 128;
        int dst = l * 65536 + j * 256 + 128 + k;
        split2(whh[j * 128 + k], d_Brz_hi[dst], d_Brz_lo[dst]);
        return;
    }
    idx -= R2_;
    if (idx < R3_) {
        int j = idx / 128, k = idx % 128;
        split2(whh[(256 + j) * 128 + k], d_Bhn_hi[idx], d_Bhn_lo[idx]);
        return;
    }
    idx -= R3_;
    if (idx < R4_) {
        float b;
        if (idx < 256)      b = bih[idx] + bhh[idx];
        else if (idx < 384) b = bih[idx];
        else                b = bhh[idx - 128];
        d_bias[idx] = b;
        return;
    }
    idx -= R4_;
    if (idx < R5_) { d_counts[idx] = 0; return; }
    idx -= R5_;
    if (idx < R6_) {
        float4 v = reinterpret_cast<const float4*>(x)[idx];
        ushort4 h, l;
        split2(v.x, h.x, l.x); split2(v.y, h.y, l.y);
        split2(v.z, h.z, l.z); split2(v.w, h.w, l.w);
        reinterpret_cast<ushort4*>(d_hsp_hi)[idx] = h;
        reinterpret_cast<ushort4*>(d_hsp_lo)[idx] = l;
    }
}

// ======================= CSR build =======================
__global__ void hist_kernel(const int* __restrict__ ei) {
    int e = blockIdx.x * blockDim.x + threadIdx.x;
    if (e < EE_) atomicAdd(&d_counts[ei[EE_ + e]], 1);
}

// parallel block scan (warp shuffles, no serial 1024-loop)
__global__ void scan_kernel() {
    __shared__ int wsum[32];
    const int CH = (NN_ + 1023) / 1024;
    int t = threadIdx.x;
    int lane = t & 31, w = t >> 5;
    int start = t * CH;
    int end = start + CH; if (end > NN_) end = NN_;
    int s = 0;
    for (int i = start; i < end; i++) s += d_counts[i];
    // inclusive warp scan of s
    int v = s;
#pragma unroll
    for (int off = 1; off < 32; off <<= 1) {
        int n = __shfl_up_sync(0xFFFFFFFFu, v, off);
        if (lane >= off) v += n;
    }
    if (lane == 31) wsum[w] = v;
    __syncthreads();
    if (w == 0) {
        int x = wsum[lane];
#pragma unroll
        for (int off = 1; off < 32; off <<= 1) {
            int n = __shfl_up_sync(0xFFFFFFFFu, x, off);
            if (lane >= off) x += n;
        }
        wsum[lane] = x;
    }
    __syncthreads();
    int excl = v - s + (w > 0 ? wsum[w - 1] : 0);
    if (t == 1023) d_rowptr[NN_] = excl + s;
    int acc = excl;
    for (int i = start; i < end; i++) {
        d_rowptr[i] = acc; d_cursor[i] = acc; acc += d_counts[i];
    }
}

__global__ void scatter_kernel(const int* __restrict__ ei) {
    int e = blockIdx.x * blockDim.x + threadIdx.x;
    if (e < EE_) {
        int dst = ei[EE_ + e];
        int pos = atomicAdd(&d_cursor[dst], 1);
        d_csr_eid[pos] = e;
    }
}

// sort segment eids (deterministic order) AND materialize src/w directly
__global__ void sortfill_kernel(const int* __restrict__ ei, const float* __restrict__ ew) {
    int n = blockIdx.x * blockDim.x + threadIdx.x;
    if (n >= NN_) return;
    int lo = d_rowptr[n], hi = d_rowptr[n + 1];
    int cnt = hi - lo;
    if (cnt <= 0) return;
    if (cnt <= 64) {
        int buf[64];
        for (int i = 0; i < cnt; i++) buf[i] = d_csr_eid[lo + i];
        for (int i = 1; i < cnt; i++) {
            int k = buf[i];
            int j = i - 1;
            while (j >= 0 && buf[j] > k) { buf[j + 1] = buf[j]; j--; }
            buf[j + 1] = k;
        }
        for (int i = 0; i < cnt; i++) {
            int eid = buf[i];
            d_csr_src[lo + i] = ei[eid];
            d_csr_w[lo + i]   = ew[eid];
        }
    } else {
        for (int i = lo + 1; i < hi; i++) {
            int ke = d_csr_eid[i];
            int j = i - 1;
            while (j >= lo && d_csr_eid[j] > ke) {
                d_csr_eid[j + 1] = d_csr_eid[j];
                j--;
            }
            d_csr_eid[j + 1] = ke;
        }
        for (int i = lo; i < hi; i++) {
            int eid = d_csr_eid[i];
            d_csr_src[i] = ei[eid];
            d_csr_w[i]   = ew[eid];
        }
    }
}

// ======================= aggregation: broadcast loads + 2-edge unroll =======================
__device__ __forceinline__ float4 agg_row(const float* __restrict__ xext, int use_x,
                                          int s, int lane) {
    float4 v;
    if (use_x) {
        v = __ldg(reinterpret_cast<const float4*>(xext + (size_t)s * CC_ + lane * 4));
    } else {
        size_t o = (size_t)s * CC_ + lane * 4;
        ushort4 vh = *reinterpret_cast<const ushort4*>(d_hsp_hi + o);
        ushort4 vl = *reinterpret_cast<const ushort4*>(d_hsp_lo + o);
        v.x = bfu(vh.x) + bfu(vl.x); v.y = bfu(vh.y) + bfu(vl.y);
        v.z = bfu(vh.z) + bfu(vl.z); v.w = bfu(vh.w) + bfu(vl.w);
    }
    return v;
}

__global__ void aggregate_kernel(const float* __restrict__ xext, int use_x) {
    int gw = (blockIdx.x * blockDim.x + threadIdx.x) >> 5;
    int lane = threadIdx.x & 31;
    if (gw >= NN_) return;
    int lo = d_rowptr[gw], hi = d_rowptr[gw + 1];
    float4 a0 = make_float4(0.f, 0.f, 0.f, 0.f);
    float4 a1 = make_float4(0.f, 0.f, 0.f, 0.f);
    int e = lo;
    for (; e + 2 <= hi; e += 2) {
        int s0 = __ldg(&d_csr_src[e]);
        int s1 = __ldg(&d_csr_src[e + 1]);
        float w0 = __ldg(&d_csr_w[e]);
        float w1 = __ldg(&d_csr_w[e + 1]);
        float4 v0 = agg_row(xext, use_x, s0, lane);
        float4 v1 = agg_row(xext, use_x, s1, lane);
        a0.x += w0 * v0.x; a0.y += w0 * v0.y; a0.z += w0 * v0.z; a0.w += w0 * v0.w;
        a1.x += w1 * v1.x; a1.y += w1 * v1.y; a1.z += w1 * v1.z; a1.w += w1 * v1.w;
    }
    if (e < hi) {
        int s0 = __ldg(&d_csr_src[e]);
        float w0 = __ldg(&d_csr_w[e]);
        float4 v0 = agg_row(xext, use_x, s0, lane);
        a0.x += w0 * v0.x; a0.y += w0 * v0.y; a0.z += w0 * v0.z; a0.w += w0 * v0.w;
    }
    a0.x += a1.x; a0.y += a1.y; a0.z += a1.z; a0.w += a1.w;
    ushort4 h, l;
    split2(a0.x, h.x, l.x); split2(a0.y, h.y, l.y);
    split2(a0.z, h.z, l.z); split2(a0.w, h.w, l.w);
    size_t o = ((size_t)gw * CC_ + lane * 4) / 4;
    reinterpret_cast<ushort4*>(d_agg_hi)[o] = h;
    reinterpret_cast<ushort4*>(d_agg_lo)[o] = l;
}

// ======================= GRU GEMM: grid (4, Ny), 64x64 warp tiles, single-sync pipe =======================
#define TSK 40
#define TILE_E (128 * TSK)
#define BUF_E  (4 * TILE_E)
#define GEMM_SMEM (2 * BUF_E * 2)   // 81920 bytes
#define EPI_S 132

template <int NCK>
__device__ __forceinline__ void gemm_body(
    char* smem, uint32_t su, int row0, int outc0,
    const unsigned short* A0hi, const unsigned short* A0lo,
    const unsigned short* A1hi, const unsigned short* A1lo,
    const unsigned short* Bhi, const unsigned short* Blo) {
    const int Kb = NCK * 32;
    __nv_bfloat16* s = reinterpret_cast<__nv_bfloat16*>(smem);
    float* sC = reinterpret_cast<float*>(smem);
    int tid = threadIdx.x, wid = tid >> 5;     // 128 threads, 4 warps
    int warp_m = wid >> 1, warp_n = wid & 1;   // 2x2 warp grid, 64x64 tiles

    wmma::fragment<wmma::accumulator, 16, 16, 16, float> acc[4][4];
#pragma unroll
    for (int i = 0; i < 4; i++)
#pragma unroll
        for (int j = 0; j < 4; j++) wmma::fill_fragment(acc[i][j], 0.f);

    auto prefetch = [&](int c, int bsel) {
        int k0 = c * 32;
        const unsigned short* Ah = A0hi;
        const unsigned short* Al = A0lo;
        int koff = k0;
        if (k0 >= 128) { Ah = A1hi; Al = A1lo; koff = k0 - 128; }
        uint32_t sb = su + (uint32_t)bsel * (BUF_E * 2);
#pragma unroll
        for (int t = 0; t < 4; t++) {
            int v = tid + t * 128;
            int r = v >> 2, c8 = (v & 3) << 3;
            uint32_t so = (uint32_t)(r * TSK + c8) * 2;
            int grow = row0 + r;
            int ok = (grow < NN_) ? 16 : 0;
            size_t ga = (size_t)grow * CC_ + koff + c8;
            cpa16(sb + so,         Ah + ga, ok);
            cpa16(sb + 10240 + so, Al + ga, ok);
            size_t gb = (size_t)r * Kb + k0 + c8;
            cpa16(sb + 20480 + so, Bhi + gb, 16);
            cpa16(sb + 30720 + so, Blo + gb, 16);
        }
    };

    prefetch(0, 0);
    CP_COMMIT();

#pragma unroll
    for (int c = 0; c < NCK; c++) {
        CP_WAIT0();
        __syncthreads();
        if (c + 1 < NCK) {
            prefetch(c + 1, (c + 1) & 1);
            CP_COMMIT();
        }

        const __nv_bfloat16* sb   = s + (c & 1) * BUF_E;
        const __nv_bfloat16* tAhi = sb;
        const __nv_bfloat16* tAlo = sb + TILE_E;
        const __nv_bfloat16* tBhi = sb + 2 * TILE_E;
        const __nv_bfloat16* tBlo = sb + 3 * TILE_E;

#pragma unroll
        for (int ks = 0; ks < 2; ks++) {
            wmma::fragment<wmma::matrix_a, 16, 16, 16, __nv_bfloat16, wmma::row_major> fahi[4], falo[4];
#pragma unroll
            for (int i = 0; i < 4; i++) {
                int off = (warp_m * 64 + i * 16) * TSK + ks * 16;
                wmma::load_matrix_sync(fahi[i], tAhi + off, TSK);
                wmma::load_matrix_sync(falo[i], tAlo + off, TSK);
            }
#pragma unroll
            for (int j = 0; j < 4; j++) {
                wmma::fragment<wmma::matrix_b, 16, 16, 16, __nv_bfloat16, wmma::col_major> fbhi, fblo;
                int off = (warp_n * 64 + j * 16) * TSK + ks * 16;
                wmma::load_matrix_sync(fbhi, tBhi + off, TSK);
                wmma::load_matrix_sync(fblo, tBlo + off, TSK);
#pragma unroll
                for (int i = 0; i < 4; i++) {
                    wmma::mma_sync(acc[i][j], fahi[i], fbhi, acc[i][j]);
                    wmma::mma_sync(acc[i][j], fahi[i], fblo, acc[i][j]);
                    wmma::mma_sync(acc[i][j], falo[i], fbhi, acc[i][j]);
                }
            }
        }
    }

    // ---- epilogue (no bias; gate adds it) ----
    if (row0 + 128 <= NN_) {
#pragma unroll
        for (int i = 0; i < 4; i++)
#pragma unroll
            for (int j = 0; j < 4; j++) {
                float* p = d_g + (size_t)(row0 + warp_m * 64 + i * 16) * 512
                           + outc0 + warp_n * 64 + j * 16;
                wmma::store_matrix_sync(p, acc[i][j], 512, wmma::mem_row_major);
            }
    } else {
        __syncthreads();
#pragma unroll
        for (int i = 0; i < 4; i++)
#pragma unroll
            for (int j = 0; j < 4; j++) {
                float* p = sC + (warp_m * 64 + i * 16) * EPI_S + warp_n * 64 + j * 16;
                wmma::store_matrix_sync(p, acc[i][j], EPI_S, wmma::mem_row_major);
            }
        __syncthreads();
#pragma unroll
        for (int t = 0; t < 32; t++) {
            int v = tid + t * 128;
            int r = v >> 5;
            int c4 = (v & 31) << 2;
            int grow = row0 + r;
            if (grow >= NN_) continue;
            float4 o;
            o.x = sC[r * EPI_S + c4 + 0];
            o.y = sC[r * EPI_S + c4 + 1];
            o.z = sC[r * EPI_S + c4 + 2];
            o.w = sC[r * EPI_S + c4 + 3];
            *reinterpret_cast<float4*>(d_g + (size_t)grow * 512 + outc0 + c4) = o;
        }
    }
}

__global__ void __launch_bounds__(128, 2)
gru_gemm_kernel(int layer) {
    extern __shared__ __align__(16) char smem[];
    uint32_t su = smem_u32(smem);
    int bx = blockIdx.x;
    int row0 = blockIdx.y * 128;

    if (bx < 2) {
        gemm_body<8>(smem, su, row0, bx * 128,
                     d_agg_hi, d_agg_lo, d_hsp_hi, d_hsp_lo,
                     d_Brz_hi + layer * 65536 + bx * 128 * 256,
                     d_Brz_lo + layer * 65536 + bx * 128 * 256);
    } else if (bx == 2) {
        gemm_body<4>(smem, su, row0, 256,
                     d_agg_hi, d_agg_lo, nullptr, nullptr,
                     d_Bxn_hi + layer * 16384, d_Bxn_lo + layer * 16384);
    } else {
        gemm_body<4>(smem, su, row0, 384,
                     d_hsp_hi, d_hsp_lo, nullptr, nullptr,
                     d_Bhn_hi, d_Bhn_lo);
    }
}

// ======================= GRU gate: 4 channels/thread, MUFU transcendentals =======================
__global__ void gate_kernel(const float* __restrict__ xext, int use_x) {
    int idx = blockIdx.x * blockDim.x + threadIdx.x;   // NN_*32 threads
    if (idx >= NN_ * 32) return;
    int node = idx >> 5;
    int c4   = (idx & 31) << 2;
    const float* g = d_g + (size_t)node * 512;
    float4 rv = __ldg(reinterpret_cast<const float4*>(g + c4));
    float4 zv = __ldg(reinterpret_cast<const float4*>(g + 128 + c4));
    float4 xn = __ldg(reinterpret_cast<const float4*>(g + 256 + c4));
    float4 hn = __ldg(reinterpret_cast<const float4*>(g + 384 + c4));
    float4 br = __ldg(reinterpret_cast<const float4*>(d_bias + c4));
    float4 bz = __ldg(reinterpret_cast<const float4*>(d_bias + 128 + c4));
    float4 bx = __ldg(reinterpret_cast<const float4*>(d_bias + 256 + c4));
    float4 bh = __ldg(reinterpret_cast<const float4*>(d_bias + 384 + c4));
    size_t ho = (size_t)node * CC_ + c4;
    float hp[4];
    if (use_x) {
        float4 v = __ldg(reinterpret_cast<const float4*>(xext + ho));
        hp[0] = v.x; hp[1] = v.y; hp[2] = v.z; hp[3] = v.w;
    } else {
        ushort4 vh = *reinterpret_cast<const ushort4*>(d_hsp_hi + ho);
        ushort4 vl = *reinterpret_cast<const ushort4*>(d_hsp_lo + ho);
        hp[0] = bfu(vh.x) + bfu(vl.x); hp[1] = bfu(vh.y) + bfu(vl.y);
        hp[2] = bfu(vh.z) + bfu(vl.z); hp[3] = bfu(vh.w) + bfu(vl.w);
    }
    float rr[4] = {rv.x + br.x, rv.y + br.y, rv.z + br.z, rv.w + br.w};
    float zz[4] = {zv.x + bz.x, zv.y + bz.y, zv.z + bz.z, zv.w + bz.w};
    float xx[4] = {xn.x + bx.x, xn.y + bx.y, xn.z + bx.z, xn.w + bx.w};
    float hh[4] = {hn.x + bh.x, hn.y + bh.y, hn.z + bh.z, hn.w + bh.w};
    ushort4 oh, ol;
    unsigned short* po = reinterpret_cast<unsigned short*>(&oh);
    unsigned short* pl = reinterpret_cast<unsigned short*>(&ol);
#pragma unroll
    for (int q = 0; q < 4; q++) {
        float r = fast_sigmoid(rr[q]);
        float z = fast_sigmoid(zz[q]);
        float n = fast_tanh(xx[q] + r * hh[q]);
        split2((1.f - z) * n + z * hp[q], po[q], pl[q]);
    }
    *reinterpret_cast<ushort4*>(d_hsp_hi + ho) = oh;
    *reinterpret_cast<ushort4*>(d_hsp_lo + ho) = ol;
}

// ======================= fused MLP + head =======================
__global__ void __launch_bounds__(256)
mlp_head_kernel(const float* __restrict__ w0, const float* __restrict__ b0,
                const float* __restrict__ w1, const float* __restrict__ b1,
                const float* __restrict__ w2, const float* __restrict__ b2,
                const float* __restrict__ w3, const float* __restrict__ b3,
                float* __restrict__ out) {
    __shared__ float sw0[HID_ * CC_];
    __shared__ float sw1[HID_ * HID_];
    __shared__ float sw2[HID_ * HID_];
    __shared__ float sw3[NCLS_ * HID_];
    __shared__ float sb0[HID_], sb1[HID_], sb2[HID_], sb3[NCLS_];
    int tid = threadIdx.x;
    for (int i = tid; i < HID_ * CC_; i += 256) sw0[i] = w0[i];
    for (int i = tid; i < HID_ * HID_; i += 256) { sw1[i] = w1[i]; sw2[i] = w2[i]; }
    for (int i = tid; i < NCLS_ * HID_; i += 256) sw3[i] = w3[i];
    if (tid < HID_) { sb0[tid] = b0[tid]; sb1[tid] = b1[tid]; sb2[tid] = b2[tid]; }
    if (tid < NCLS_) sb3[tid] = b3[tid];
    __syncthreads();

    int n = blockIdx.x * 256 + tid;
    if (n >= NN_) return;

    float y0[HID_];
#pragma unroll
    for (int o = 0; o < HID_; o++) y0[o] = sb0[o];

#pragma unroll
    for (int ck = 0; ck < 8; ck++) {
        float hb[16];
        size_t go = (size_t)n * CC_ + ck * 16;
        ushort4 h0 = *reinterpret_cast<const ushort4*>(d_hsp_hi + go);
        ushort4 h1 = *reinterpret_cast<const ushort4*>(d_hsp_hi + go + 4);
        ushort4 h2 = *reinterpret_cast<const ushort4*>(d_hsp_hi + go + 8);
        ushort4 h3 = *reinterpret_cast<const ushort4*>(d_hsp_hi + go + 12);
        ushort4 l0 = *reinterpret_cast<const ushort4*>(d_hsp_lo + go);
        ushort4 l1 = *reinterpret_cast<const ushort4*>(d_hsp_lo + go + 4);
        ushort4 l2 = *reinterpret_cast<const ushort4*>(d_hsp_lo + go + 8);
        ushort4 l3 = *reinterpret_cast<const ushort4*>(d_hsp_lo + go + 12);
        hb[0]  = bfu(h0.x) + bfu(l0.x); hb[1]  = bfu(h0.y) + bfu(l0.y);
        hb[2]  = bfu(h0.z) + bfu(l0.z); hb[3]  = bfu(h0.w) + bfu(l0.w);
        hb[4]  = bfu(h1.x) + bfu(l1.x); hb[5]  = bfu(h1.y) + bfu(l1.y);
        hb[6]  = bfu(h1.z) + bfu(l1.z); hb[7]  = bfu(h1.w) + bfu(l1.w);
        hb[8]  = bfu(h2.x) + bfu(l2.x); hb[9]  = bfu(h2.y) + bfu(l2.y);
        hb[10] = bfu(h2.z) + bfu(l2.z); hb[11] = bfu(h2.w) + bfu(l2.w);
        hb[12] = bfu(h3.x) + bfu(l3.x); hb[13] = bfu(h3.y) + bfu(l3.y);
        hb[14] = bfu(h3.z) + bfu(l3.z); hb[15] = bfu(h3.w) + bfu(l3.w);
#pragma unroll
        for (int o = 0; o < HID_; o++) {
            const float4* wr = reinterpret_cast<const float4*>(sw0 + o * CC_ + ck * 16);
            float4 w4;
            w4 = wr[0]; y0[o] += hb[0] * w4.x + hb[1] * w4.y + hb[2] * w4.z + hb[3] * w4.w;
            w4 = wr[1]; y0[o] += hb[4] * w4.x + hb[5] * w4.y + hb[6] * w4.z + hb[7] * w4.w;
            w4 = wr[2]; y0[o] += hb[8] * w4.x + hb[9] * w4.y + hb[10] * w4.z + hb[11] * w4.w;
            w4 = wr[3]; y0[o] += hb[12] * w4.x + hb[13] * w4.y + hb[14] * w4.z + hb[15] * w4.w;
        }
    }
#pragma unroll
    for (int o = 0; o < HID_; o++) y0[o] = fast_tanh(y0[o]);

    float y1[HID_];
#pragma unroll
    for (int o = 0; o < HID_; o++) {
        float s = sb1[o];
        const float4* wr = reinterpret_cast<const float4*>(sw1 + o * HID_);
#pragma unroll
        for (int k4 = 0; k4 < HID_ / 4; k4++) {
            float4 w4 = wr[k4];
            s += y0[k4 * 4] * w4.x + y0[k4 * 4 + 1] * w4.y + y0[k4 * 4 + 2] * w4.z + y0[k4 * 4 + 3] * w4.w;
        }
        y1[o] = fast_tanh(s);
    }
#pragma unroll
    for (int o = 0; o < HID_; o++) {
        float s = sb2[o];
        const float4* wr = reinterpret_cast<const float4*>(sw2 + o * HID_);
#pragma unroll
        for (int k4 = 0; k4 < HID_ / 4; k4++) {
            float4 w4 = wr[k4];
            s += y1[k4 * 4] * w4.x + y1[k4 * 4 + 1] * w4.y + y1[k4 * 4 + 2] * w4.z + y1[k4 * 4 + 3] * w4.w;
        }
        y0[o] = fast_tanh(s);
    }

    float logit[NCLS_];
    float mx = -1e30f;
#pragma unroll
    for (int c = 0; c < NCLS_; c++) {
        float s = sb3[c];
        const float4* wr = reinterpret_cast<const float4*>(sw3 + c * HID_);
#pragma unroll
        for (int k4 = 0; k4 < HID_ / 4; k4++) {
            float4 w4 = wr[k4];
            s += y0[k4 * 4] * w4.x + y0[k4 * 4 + 1] * w4.y + y0[k4 * 4 + 2] * w4.z + y0[k4 * 4 + 3] * w4.w;
        }
        logit[c] = s;
        mx = fmaxf(mx, s);
    }
    float se = 0.f;
#pragma unroll
    for (int c = 0; c < NCLS_; c++) se += __expf(logit[c] - mx);
    float lse = __logf(se) + mx;
#pragma unroll
    for (int c = 0; c < NCLS_; c++) out[(size_t)n * NCLS_ + c] = logit[c] - lse;
}

// ======================= host: kernel launches only =======================
extern "C" void kernel_launch(void* const* d_in, const int* in_sizes, int n_in,
                              void* d_out, int out_size) {
    const float* x    = (const float*)d_in[0];
    const int*   ei   = (const int*)  d_in[1];
    const float* ew   = (const float*)d_in[2];
    const float* cw   = (const float*)d_in[3];
    const float* w_ih = (const float*)d_in[4];
    const float* w_hh = (const float*)d_in[5];
    const float* b_ih = (const float*)d_in[6];
    const float* b_hh = (const float*)d_in[7];
    const float* w0   = (const float*)d_in[8];
    const float* b0   = (const float*)d_in[9];
    const float* w1   = (const float*)d_in[10];
    const float* b1   = (const float*)d_in[11];
    const float* w2   = (const float*)d_in[12];
    const float* b2   = (const float*)d_in[13];
    const float* w3   = (const float*)d_in[14];
    const float* b3   = (const float*)d_in[15];
    float* out = (float*)d_out;

    cudaFuncSetAttribute(gru_gemm_kernel, cudaFuncAttributeMaxDynamicSharedMemorySize,
                         GEMM_SMEM);

    // init (weights/bias/counts/x-split)
    {
        int total = R1_ + R2_ + R3_ + R4_ + R5_ + R6_;
        init_kernel<<<(total + 255) / 256, 256>>>(cw, w_ih, w_hh, b_ih, b_hh, x);
    }
    // CSR build
    hist_kernel<<<(EE_ + 255) / 256, 256>>>(ei);
    scan_kernel<<<1, 1024>>>();
    scatter_kernel<<<(EE_ + 255) / 256, 256>>>(ei);
    sortfill_kernel<<<(NN_ + 255) / 256, 256>>>(ei, ew);

    dim3 grid_g(4, (NN_ + 127) / 128);
    for (int l = 0; l < LL_; l++) {
        aggregate_kernel<<<(NN_ * 32 + 255) / 256, 256>>>(x, l == 0 ? 1 : 0);
        gru_gemm_kernel<<<grid_g, 128, GEMM_SMEM>>>(l);
        gate_kernel<<<(NN_ * 32 + 255) / 256, 256>>>(x, l == 0 ? 1 : 0);
    }

    mlp_head_kernel<<<(NN_ + 255) / 256, 256>>>(w0, b0, w1, b1, w2, b2, w3, b3, out);
}